// round 13
// baseline (speedup 1.0000x reference)
#include <cuda_runtime.h>
#include <cuda_fp16.h>
#include <cstdint>
#include <math.h>

#define Nn 8192
#define Ff 128
#define ALPHAv 0.2f
#define LOG2E 1.4426950408889634f

// ---- scratch (device globals; no allocation allowed) ----
__device__ __half g_hb[Nn * Ff];            // h in fp16, row-major [j][f]
__device__ float g_ssrc[Nn];                // scaled by LOG2E
__device__ float g_sdst[Nn];                // scaled by LOG2E
__device__ unsigned int g_smax_enc;         // order-monotone encoded max (idempotent)
__device__ float g_part[2 * Nn * Ff];       // unnormalized partial outputs
__device__ float g_lpart[2 * Nn];           // partial l sums
__device__ unsigned int g_done[Nn / 64];    // per row-group arrival counters (self-resetting)

__device__ __forceinline__ uint32_t smem_u32(const void* p) {
    uint32_t a;
    asm("{ .reg .u64 t; cvta.to.shared.u64 t, %1; cvt.u32.u64 %0, t; }"
        : "=r"(a) : "l"(p));
    return a;
}
__device__ __forceinline__ unsigned int enc_f(float f) {
    unsigned int b = __float_as_uint(f);
    return (b & 0x80000000u) ? ~b : (b | 0x80000000u);
}
__device__ __forceinline__ float dec_f(unsigned int u) {
    unsigned int b = (u & 0x80000000u) ? (u ^ 0x80000000u) : ~u;
    return __uint_as_float(b);
}
__device__ __forceinline__ uint32_t hexp2(uint32_t packed_h2) {
    uint32_t r;
    asm("ex2.approx.f16x2 %0, %1;" : "=r"(r) : "r"(packed_h2));
    return r;
}

// ---------------------------------------------------------------------------
// K1: h = x @ W, 256 threads, 32 rows/CTA (grid 256). fp16 h + scores + smax.
// ---------------------------------------------------------------------------
__global__ void __launch_bounds__(256) k_xw(const float* __restrict__ x,
                                            const float* __restrict__ W,
                                            const float* __restrict__ a) {
    __shared__ __align__(16) float hsm[32 * 132];
    int tid = threadIdx.x;
    int i0 = blockIdx.x * 32;
    int f = tid & 127, rq = tid >> 7;  // rq: half (16 rows)

#pragma unroll
    for (int t = 0; t < 16; ++t)
        hsm[(rq * 16 + t) * 132 + f] = x[(size_t)(i0 + rq * 16 + t) * Ff + f];
    __syncthreads();

    float acc[16];
#pragma unroll
    for (int r = 0; r < 16; ++r) acc[r] = 0.f;

    float w[8], wn[8];
#pragma unroll
    for (int u = 0; u < 8; ++u) w[u] = __ldg(W + u * Ff + f);

    for (int k = 0; k < Ff; k += 8) {
        if (k < Ff - 8) {
#pragma unroll
            for (int u = 0; u < 8; ++u) wn[u] = __ldg(W + (k + 8 + u) * Ff + f);
        }
#pragma unroll
        for (int r = 0; r < 16; ++r) {
            const float* xr = &hsm[(rq * 16 + r) * 132 + k];
            float4 x0 = *(const float4*)xr;
            float4 x1 = *(const float4*)(xr + 4);
            acc[r] = fmaf(x0.x, w[0], acc[r]);
            acc[r] = fmaf(x0.y, w[1], acc[r]);
            acc[r] = fmaf(x0.z, w[2], acc[r]);
            acc[r] = fmaf(x0.w, w[3], acc[r]);
            acc[r] = fmaf(x1.x, w[4], acc[r]);
            acc[r] = fmaf(x1.y, w[5], acc[r]);
            acc[r] = fmaf(x1.z, w[6], acc[r]);
            acc[r] = fmaf(x1.w, w[7], acc[r]);
        }
#pragma unroll
        for (int u = 0; u < 8; ++u) w[u] = wn[u];
    }
    __syncthreads();

#pragma unroll
    for (int r = 0; r < 16; ++r) {
        int row = rq * 16 + r;
        hsm[row * 132 + f] = acc[r];
        g_hb[(size_t)(i0 + row) * Ff + f] = __float2half(acc[r]);
    }
    __syncthreads();

    // scores: 8 threads per row, 16 features each (32 rows x 8 = 256 threads)
    int row = tid >> 3, c = tid & 7;
    float p1 = 0.f, p2 = 0.f;
#pragma unroll
    for (int i = 0; i < 16; ++i) {
        float hv = hsm[row * 132 + c * 16 + i];
        p1 = fmaf(hv, __ldg(a + c * 16 + i), p1);
        p2 = fmaf(hv, __ldg(a + Ff + c * 16 + i), p2);
    }
    p1 += __shfl_xor_sync(0xffffffffu, p1, 1);
    p1 += __shfl_xor_sync(0xffffffffu, p1, 2);
    p1 += __shfl_xor_sync(0xffffffffu, p1, 4);
    p2 += __shfl_xor_sync(0xffffffffu, p2, 1);
    p2 += __shfl_xor_sync(0xffffffffu, p2, 2);
    p2 += __shfl_xor_sync(0xffffffffu, p2, 4);
    if (c == 0) {
        float sd = p2 * LOG2E;
        g_ssrc[i0 + row] = p1 * LOG2E;
        g_sdst[i0 + row] = sd;
        atomicMax(&g_smax_enc, enc_f(sd));  // idempotent across graph replays
    }
}

// ---------------------------------------------------------------------------
// K_main: grid 256 (128 row-groups x 2 j-halves), 256 thr, warp tile m32xn32,
// 2 CTAs/SM. adj read dense (2 rows x 256B per warp-LDG). Last CTA of each
// row-group pair combines partials and writes out (fused k_combine).
// ---------------------------------------------------------------------------
__device__ __forceinline__ void mma16816(float* d, const uint32_t* A,
                                         uint32_t b0, uint32_t b1) {
    asm volatile(
        "mma.sync.aligned.m16n8k16.row.col.f32.f16.f16.f32 "
        "{%0,%1,%2,%3}, {%4,%5,%6,%7}, {%8,%9}, {%0,%1,%2,%3};"
        : "+f"(d[0]), "+f"(d[1]), "+f"(d[2]), "+f"(d[3])
        : "r"(A[0]), "r"(A[1]), "r"(A[2]), "r"(A[3]), "r"(b0), "r"(b1));
}

#define QBUF_OFF 0
#define HBUF_OFF 16384
#define SDST_OFF 49152
#define SMEM_SZ  57344

__global__ void __launch_bounds__(256, 2) k_main(const int* __restrict__ adj,
                                                 float* __restrict__ out) {
    extern __shared__ __align__(16) char smem[];
    __shared__ unsigned int s_old;
    char* qbuf = smem + QBUF_OFF;
    char* sdst_sm = smem + SDST_OFF;
    uint32_t qb32 = smem_u32(smem + QBUF_OFF);
    uint32_t hb32 = smem_u32(smem + HBUF_OFF);

    int tid = threadIdx.x, lane = tid & 31, wid = tid >> 5;
    int ws = wid & 1, ns = wid >> 1;
    int bid = blockIdx.x;
    int i0 = (bid >> 1) * 64;
    int jh = bid & 1;
    int joff = jh * 4096;

    // ---- stage this half's sdst fp32 -> fp16 smem (4096 values) ----
    {
        const float4* sp = (const float4*)(g_sdst + joff);
        uint2* dp = (uint2*)sdst_sm;
#pragma unroll
        for (int u = 0; u < 4; ++u) {
            float4 v = __ldg(sp + tid * 4 + u);
            __half2 h0 = __floats2half2_rn(v.x, v.y);
            __half2 h1 = __floats2half2_rn(v.z, v.w);
            dp[tid * 4 + u] = make_uint2(*(uint32_t*)&h0, *(uint32_t*)&h1);
        }
    }

    // ---- q constants: thread owns 4 j's (lj*4..lj*4+3) in 4 rows ----
    int hs = lane >> 4, lj = lane & 15;
    float S = dec_f(g_smax_enc);
    __half2 sA2[4], nB2[4];
    uint32_t q_sts[4];
    const int4* ap[4];
#pragma unroll
    for (int u = 0; u < 4; ++u) {
        int r = wid * 8 + 2 * u + hs;
        float sA = g_ssrc[i0 + r];
        float tAx = sA + S;
        float nB = -fmaxf(tAx, ALPHAv * tAx);
        sA2[u] = __floats2half2_rn(sA, sA);
        nB2[u] = __floats2half2_rn(nB, nB);
        q_sts[u] = (uint32_t)(r * 128 + (((lj >> 1) ^ (r & 7)) << 4) + (lj & 1) * 8);
        ap[u] = (const int4*)(adj + (size_t)(i0 + r) * Nn + joff + lj * 4);
    }
    __half2 c02 = __floats2half2_rn(ALPHAv, ALPHAv);
    float lacc[4] = {0.f, 0.f, 0.f, 0.f};

    // ---- H cp.async: 1 row, 4 chunks of 16B per thread ----
    int hrow = tid >> 2, hc = tid & 3;
    uint32_t h_sts[4];
#pragma unroll
    for (int u = 0; u < 4; ++u)
        h_sts[u] = (uint32_t)(hrow * 256 + (((hc * 4 + u) ^ (hrow & 7)) << 4));
    const char* hsrc_base = (const char*)g_hb + ((size_t)(joff + hrow) * Ff + hc * 32) * 2;

    // ---- mma addressing ----
    int lgroup = lane >> 3;
    int lrow_in = (lgroup & 1) * 8 + (lane & 7);
    int bchunk = ns * 4 + (lgroup >> 1);
    int arow = ws * 32 + (lane & 15);
    int arx = arow & 7;
    uint32_t a_base = (uint32_t)(arow * 128);
    int asel = lane >> 4;

    float acc[2][4][4];
#pragma unroll
    for (int mb = 0; mb < 2; ++mb)
#pragma unroll
        for (int nb = 0; nb < 4; ++nb)
#pragma unroll
            for (int k = 0; k < 4; ++k) acc[mb][nb][k] = 0.f;

    // ---- prologue: H(0) cp.async + adj(0) ----
#pragma unroll
    for (int u = 0; u < 4; ++u)
        asm volatile("cp.async.cg.shared.global [%0], [%1], 16;"
                     :: "r"(hb32 + h_sts[u]), "l"(hsrc_base + u * 16) : "memory");
    asm volatile("cp.async.commit_group;" ::: "memory");

    int4 av[4];
#pragma unroll
    for (int u = 0; u < 4; ++u) av[u] = __ldg(ap[u]);
    __syncthreads();  // sdst visible

    // ---- q(0) ----
    {
        uint2 sd = *(const uint2*)(sdst_sm + lj * 8);
        __half2 sd0 = *(__half2*)&sd.x, sd1 = *(__half2*)&sd.y;
#pragma unroll
        for (int u = 0; u < 4; ++u) {
            __half2 t0 = __hadd2(sd0, sA2[u]);
            __half2 t1 = __hadd2(sd1, sA2[u]);
            __half2 m0 = __hadd2(__hmax2(t0, __hmul2(t0, c02)), nB2[u]);
            __half2 m1 = __hadd2(__hmax2(t1, __hmul2(t1, c02)), nB2[u]);
            uint32_t e0 = hexp2(*(uint32_t*)&m0);
            uint32_t e1 = hexp2(*(uint32_t*)&m1);
            uint32_t k0 = (av[u].x > 0 ? 0x3C00u : 0u) | (av[u].y > 0 ? 0x3C000000u : 0u);
            uint32_t k1 = (av[u].z > 0 ? 0x3C00u : 0u) | (av[u].w > 0 ? 0x3C000000u : 0u);
            __half2 q0 = __hmul2(*(__half2*)&e0, *(__half2*)&k0);
            __half2 q1 = __hmul2(*(__half2*)&e1, *(__half2*)&k1);
            float2 f0 = __half22float2(__hadd2(q0, q1));
            lacc[u] += f0.x + f0.y;
            *(uint2*)(qbuf + q_sts[u]) = make_uint2(*(uint32_t*)&q0, *(uint32_t*)&q1);
        }
    }
    asm volatile("cp.async.wait_group 0;" ::: "memory");
    __syncthreads();  // q(0), H(0) visible

    for (int t = 0; t < 64; ++t) {
        // ---- issue H(t+1) cp.async + adj(t+1) LDGs ----
        if (t < 63) {
            int tt = t + 1;
            uint32_t dst = hb32 + (tt & 1) * 16384;
            const char* src = hsrc_base + (size_t)tt * 64 * 256;
#pragma unroll
            for (int u = 0; u < 4; ++u)
                asm volatile("cp.async.cg.shared.global [%0], [%1], 16;"
                             :: "r"(dst + h_sts[u]), "l"(src + u * 16) : "memory");
            asm volatile("cp.async.commit_group;" ::: "memory");
#pragma unroll
            for (int u = 0; u < 4; ++u) av[u] = __ldg(ap[u] + tt * 16);
        }

        // ---- MMA on tile t ----
        uint32_t qb = qb32 + (uint32_t)((t & 1) * 8192);
        uint32_t hb = hb32 + (uint32_t)((t & 1) * 16384);
#pragma unroll
        for (int kb = 0; kb < 4; ++kb) {
            uint32_t a0[4], a1[4];
            uint32_t aaddr = qb + a_base + (uint32_t)((((2 * kb + asel) ^ arx)) << 4);
            asm volatile(
                "ldmatrix.sync.aligned.m8n8.x4.shared.b16 {%0,%1,%2,%3}, [%4];"
                : "=r"(a0[0]), "=r"(a0[1]), "=r"(a0[2]), "=r"(a0[3]) : "r"(aaddr));
            asm volatile(
                "ldmatrix.sync.aligned.m8n8.x4.shared.b16 {%0,%1,%2,%3}, [%4];"
                : "=r"(a1[0]), "=r"(a1[1]), "=r"(a1[2]), "=r"(a1[3])
                : "r"(aaddr + 2048));
            int lrow = kb * 16 + lrow_in;
            int rx = lrow & 7;
            uint32_t rowa = hb + (uint32_t)(lrow * 256);
#pragma unroll
            for (int p = 0; p < 2; ++p) {
                uint32_t baddr = rowa + (uint32_t)((((bchunk + 2 * p) ^ rx)) << 4);
                uint32_t b0, b1, b2, b3;
                asm volatile(
                    "ldmatrix.sync.aligned.m8n8.x4.trans.shared.b16 "
                    "{%0,%1,%2,%3}, [%4];"
                    : "=r"(b0), "=r"(b1), "=r"(b2), "=r"(b3) : "r"(baddr));
                mma16816(acc[0][2 * p], a0, b0, b1);
                mma16816(acc[0][2 * p + 1], a0, b2, b3);
                mma16816(acc[1][2 * p], a1, b0, b1);
                mma16816(acc[1][2 * p + 1], a1, b2, b3);
            }
        }

        // ---- compute q(t+1), STS into other buffer ----
        if (t < 63) {
            int tt = t + 1;
            char* qd = qbuf + (tt & 1) * 8192;
            uint2 sd = *(const uint2*)(sdst_sm + tt * 128 + lj * 8);
            __half2 sd0 = *(__half2*)&sd.x, sd1 = *(__half2*)&sd.y;
#pragma unroll
            for (int u = 0; u < 4; ++u) {
                __half2 t0 = __hadd2(sd0, sA2[u]);
                __half2 t1 = __hadd2(sd1, sA2[u]);
                __half2 m0 = __hadd2(__hmax2(t0, __hmul2(t0, c02)), nB2[u]);
                __half2 m1 = __hadd2(__hmax2(t1, __hmul2(t1, c02)), nB2[u]);
                uint32_t e0 = hexp2(*(uint32_t*)&m0);
                uint32_t e1 = hexp2(*(uint32_t*)&m1);
                uint32_t k0 = (av[u].x > 0 ? 0x3C00u : 0u) | (av[u].y > 0 ? 0x3C000000u : 0u);
                uint32_t k1 = (av[u].z > 0 ? 0x3C00u : 0u) | (av[u].w > 0 ? 0x3C000000u : 0u);
                __half2 q0 = __hmul2(*(__half2*)&e0, *(__half2*)&k0);
                __half2 q1 = __hmul2(*(__half2*)&e1, *(__half2*)&k1);
                float2 f0 = __half22float2(__hadd2(q0, q1));
                lacc[u] += f0.x + f0.y;
                *(uint2*)(qd + q_sts[u]) = make_uint2(*(uint32_t*)&q0, *(uint32_t*)&q1);
            }
            asm volatile("cp.async.wait_group 0;" ::: "memory");
        }
        __syncthreads();
    }

    // ---- partial l: reduce over 16 lanes sharing each row ----
#pragma unroll
    for (int u = 0; u < 4; ++u) {
        lacc[u] += __shfl_xor_sync(0xffffffffu, lacc[u], 1);
        lacc[u] += __shfl_xor_sync(0xffffffffu, lacc[u], 2);
        lacc[u] += __shfl_xor_sync(0xffffffffu, lacc[u], 4);
        lacc[u] += __shfl_xor_sync(0xffffffffu, lacc[u], 8);
    }
    if (lj == 0) {
#pragma unroll
        for (int u = 0; u < 4; ++u)
            g_lpart[jh * Nn + i0 + wid * 8 + 2 * u + hs] = lacc[u];
    }

    // ---- write unnormalized partials ----
    int g = lane >> 2, c = lane & 3;
    float* pb = g_part + (size_t)jh * Nn * Ff;
#pragma unroll
    for (int mb = 0; mb < 2; ++mb) {
        int rA = ws * 32 + mb * 16 + g, rB = rA + 8;
#pragma unroll
        for (int nb = 0; nb < 4; ++nb) {
            int col = ns * 32 + nb * 8 + 2 * c;
            *(float2*)(pb + (size_t)(i0 + rA) * Ff + col) =
                make_float2(acc[mb][nb][0], acc[mb][nb][1]);
            *(float2*)(pb + (size_t)(i0 + rB) * Ff + col) =
                make_float2(acc[mb][nb][2], acc[mb][nb][3]);
        }
    }

    // ---- fused combine: last CTA of this row-group pair normalizes + writes out ----
    __threadfence();
    __syncthreads();
    if (tid == 0) s_old = atomicAdd(&g_done[bid >> 1], 1u);
    __syncthreads();
    if (s_old == 1) {
        __threadfence();  // acquire: partner's partials visible
        if (tid == 0) g_done[bid >> 1] = 0;  // reset for next graph replay
        const float4* p0 = (const float4*)g_part + (size_t)i0 * 32;
        const float4* p1 = (const float4*)(g_part + (size_t)Nn * Ff) + (size_t)i0 * 32;
        float4* op = (float4*)out + (size_t)i0 * 32;
#pragma unroll
        for (int u = 0; u < 8; ++u) {
            int idx = u * 256 + tid;     // 0..2047 float4 (64 rows x 32)
            int row = idx >> 5;
            float il = 1.0f / (g_lpart[i0 + row] + g_lpart[Nn + i0 + row]);
            float4 av4 = p0[idx], bv4 = p1[idx];
            op[idx] = make_float4((av4.x + bv4.x) * il, (av4.y + bv4.y) * il,
                                  (av4.z + bv4.z) * il, (av4.w + bv4.w) * il);
        }
    }
}

// ---------------------------------------------------------------------------
extern "C" void kernel_launch(void* const* d_in, const int* in_sizes, int n_in,
                              void* d_out, int out_size) {
    const float* x   = (const float*)d_in[0];
    const int*   adj = (const int*)d_in[1];
    const float* W   = (const float*)d_in[2];
    const float* a   = (const float*)d_in[3];
    float* out = (float*)d_out;

    cudaFuncSetAttribute(k_main, cudaFuncAttributeMaxDynamicSharedMemorySize, SMEM_SZ);

    k_xw<<<Nn / 32, 256>>>(x, W, a);
    k_main<<<Nn / 64 * 2, 256, SMEM_SZ>>>(adj, out);
}

// round 14
// speedup vs baseline: 1.0512x; 1.0512x over previous
#include <cuda_runtime.h>
#include <cuda_fp16.h>
#include <cstdint>
#include <math.h>

#define Nn 8192
#define Ff 128
#define ALPHAv 0.2f
#define LOG2E 1.4426950408889634f

// ---- scratch (device globals; no allocation allowed) ----
__device__ __half g_hb[Nn * Ff];            // h in fp16, row-major [j][f]
__device__ float g_ssrc[Nn];                // scaled by LOG2E
__device__ float g_sdst[Nn];                // scaled by LOG2E
__device__ unsigned int g_smax_enc;         // order-monotone encoded max (idempotent)
__device__ float g_part[2 * Nn * Ff];       // unnormalized partial outputs
__device__ float g_lpart[2 * Nn];           // partial l sums

__device__ __forceinline__ uint32_t smem_u32(const void* p) {
    uint32_t a;
    asm("{ .reg .u64 t; cvta.to.shared.u64 t, %1; cvt.u32.u64 %0, t; }"
        : "=r"(a) : "l"(p));
    return a;
}
__device__ __forceinline__ unsigned int enc_f(float f) {
    unsigned int b = __float_as_uint(f);
    return (b & 0x80000000u) ? ~b : (b | 0x80000000u);
}
__device__ __forceinline__ float dec_f(unsigned int u) {
    unsigned int b = (u & 0x80000000u) ? (u ^ 0x80000000u) : ~u;
    return __uint_as_float(b);
}
__device__ __forceinline__ uint32_t hexp2(uint32_t packed_h2) {
    uint32_t r;
    asm("ex2.approx.f16x2 %0, %1;" : "=r"(r) : "r"(packed_h2));
    return r;
}

// ---------------------------------------------------------------------------
// K1: h = x @ W, 256 threads, 32 rows/CTA (grid 256). fp16 h + scores + smax.
// ---------------------------------------------------------------------------
__global__ void __launch_bounds__(256) k_xw(const float* __restrict__ x,
                                            const float* __restrict__ W,
                                            const float* __restrict__ a) {
    __shared__ __align__(16) float hsm[32 * 132];
    int tid = threadIdx.x;
    int i0 = blockIdx.x * 32;
    int f = tid & 127, rq = tid >> 7;  // rq: half (16 rows)

#pragma unroll
    for (int t = 0; t < 16; ++t)
        hsm[(rq * 16 + t) * 132 + f] = x[(size_t)(i0 + rq * 16 + t) * Ff + f];
    __syncthreads();

    float acc[16];
#pragma unroll
    for (int r = 0; r < 16; ++r) acc[r] = 0.f;

    float w[8], wn[8];
#pragma unroll
    for (int u = 0; u < 8; ++u) w[u] = __ldg(W + u * Ff + f);

    for (int k = 0; k < Ff; k += 8) {
        if (k < Ff - 8) {
#pragma unroll
            for (int u = 0; u < 8; ++u) wn[u] = __ldg(W + (k + 8 + u) * Ff + f);
        }
#pragma unroll
        for (int r = 0; r < 16; ++r) {
            const float* xr = &hsm[(rq * 16 + r) * 132 + k];
            float4 x0 = *(const float4*)xr;
            float4 x1 = *(const float4*)(xr + 4);
            acc[r] = fmaf(x0.x, w[0], acc[r]);
            acc[r] = fmaf(x0.y, w[1], acc[r]);
            acc[r] = fmaf(x0.z, w[2], acc[r]);
            acc[r] = fmaf(x0.w, w[3], acc[r]);
            acc[r] = fmaf(x1.x, w[4], acc[r]);
            acc[r] = fmaf(x1.y, w[5], acc[r]);
            acc[r] = fmaf(x1.z, w[6], acc[r]);
            acc[r] = fmaf(x1.w, w[7], acc[r]);
        }
#pragma unroll
        for (int u = 0; u < 8; ++u) w[u] = wn[u];
    }
    __syncthreads();

#pragma unroll
    for (int r = 0; r < 16; ++r) {
        int row = rq * 16 + r;
        hsm[row * 132 + f] = acc[r];
        g_hb[(size_t)(i0 + row) * Ff + f] = __float2half(acc[r]);
    }
    __syncthreads();

    // scores: 8 threads per row, 16 features each (32 rows x 8 = 256 threads)
    int row = tid >> 3, c = tid & 7;
    float p1 = 0.f, p2 = 0.f;
#pragma unroll
    for (int i = 0; i < 16; ++i) {
        float hv = hsm[row * 132 + c * 16 + i];
        p1 = fmaf(hv, __ldg(a + c * 16 + i), p1);
        p2 = fmaf(hv, __ldg(a + Ff + c * 16 + i), p2);
    }
    p1 += __shfl_xor_sync(0xffffffffu, p1, 1);
    p1 += __shfl_xor_sync(0xffffffffu, p1, 2);
    p1 += __shfl_xor_sync(0xffffffffu, p1, 4);
    p2 += __shfl_xor_sync(0xffffffffu, p2, 1);
    p2 += __shfl_xor_sync(0xffffffffu, p2, 2);
    p2 += __shfl_xor_sync(0xffffffffu, p2, 4);
    if (c == 0) {
        float sd = p2 * LOG2E;
        g_ssrc[i0 + row] = p1 * LOG2E;
        g_sdst[i0 + row] = sd;
        atomicMax(&g_smax_enc, enc_f(sd));  // idempotent across graph replays
    }
}

// ---------------------------------------------------------------------------
// K_main: grid 256 (128 row-groups x 2 j-halves), 256 thr, warp tile m32xn32,
// 2 CTAs/SM. adj read dense (2 rows x 256B per warp-LDG). (R12 version.)
// ---------------------------------------------------------------------------
__device__ __forceinline__ void mma16816(float* d, const uint32_t* A,
                                         uint32_t b0, uint32_t b1) {
    asm volatile(
        "mma.sync.aligned.m16n8k16.row.col.f32.f16.f16.f32 "
        "{%0,%1,%2,%3}, {%4,%5,%6,%7}, {%8,%9}, {%0,%1,%2,%3};"
        : "+f"(d[0]), "+f"(d[1]), "+f"(d[2]), "+f"(d[3])
        : "r"(A[0]), "r"(A[1]), "r"(A[2]), "r"(A[3]), "r"(b0), "r"(b1));
}

#define QBUF_OFF 0
#define HBUF_OFF 16384
#define SDST_OFF 49152
#define SMEM_SZ  57344

__global__ void __launch_bounds__(256, 2) k_main(const int* __restrict__ adj) {
    extern __shared__ __align__(16) char smem[];
    char* qbuf = smem + QBUF_OFF;
    char* sdst_sm = smem + SDST_OFF;
    uint32_t qb32 = smem_u32(smem + QBUF_OFF);
    uint32_t hb32 = smem_u32(smem + HBUF_OFF);

    int tid = threadIdx.x, lane = tid & 31, wid = tid >> 5;
    int ws = wid & 1, ns = wid >> 1;
    int bid = blockIdx.x;
    int i0 = (bid >> 1) * 64;
    int jh = bid & 1;
    int joff = jh * 4096;

    // ---- stage this half's sdst fp32 -> fp16 smem (4096 values) ----
    {
        const float4* sp = (const float4*)(g_sdst + joff);
        uint2* dp = (uint2*)sdst_sm;
#pragma unroll
        for (int u = 0; u < 4; ++u) {
            float4 v = __ldg(sp + tid * 4 + u);
            __half2 h0 = __floats2half2_rn(v.x, v.y);
            __half2 h1 = __floats2half2_rn(v.z, v.w);
            dp[tid * 4 + u] = make_uint2(*(uint32_t*)&h0, *(uint32_t*)&h1);
        }
    }

    // ---- q constants: thread owns 4 j's (lj*4..lj*4+3) in 4 rows ----
    int hs = lane >> 4, lj = lane & 15;
    float S = dec_f(g_smax_enc);
    int qrows[4];
    __half2 sA2[4], nB2[4];
    uint32_t q_sts[4];
    const int4* ap[4];
#pragma unroll
    for (int u = 0; u < 4; ++u) {
        int r = wid * 8 + 2 * u + hs;
        qrows[u] = r;
        float sA = g_ssrc[i0 + r];
        float tAx = sA + S;
        float nB = -fmaxf(tAx, ALPHAv * tAx);
        sA2[u] = __floats2half2_rn(sA, sA);
        nB2[u] = __floats2half2_rn(nB, nB);
        q_sts[u] = (uint32_t)(r * 128 + (((lj >> 1) ^ (r & 7)) << 4) + (lj & 1) * 8);
        ap[u] = (const int4*)(adj + (size_t)(i0 + r) * Nn + joff + lj * 4);
    }
    __half2 c02 = __floats2half2_rn(ALPHAv, ALPHAv);
    float lacc[4] = {0.f, 0.f, 0.f, 0.f};

    // ---- H cp.async: 1 row, 4 chunks of 16B per thread ----
    int hrow = tid >> 2, hc = tid & 3;
    uint32_t h_sts[4];
#pragma unroll
    for (int u = 0; u < 4; ++u)
        h_sts[u] = (uint32_t)(hrow * 256 + (((hc * 4 + u) ^ (hrow & 7)) << 4));
    const char* hsrc_base = (const char*)g_hb + ((size_t)(joff + hrow) * Ff + hc * 32) * 2;

    // ---- mma addressing ----
    int lgroup = lane >> 3;
    int lrow_in = (lgroup & 1) * 8 + (lane & 7);
    int bchunk = ns * 4 + (lgroup >> 1);
    int arow = ws * 32 + (lane & 15);
    int arx = arow & 7;
    uint32_t a_base = (uint32_t)(arow * 128);
    int asel = lane >> 4;

    float acc[2][4][4];
#pragma unroll
    for (int mb = 0; mb < 2; ++mb)
#pragma unroll
        for (int nb = 0; nb < 4; ++nb)
#pragma unroll
            for (int k = 0; k < 4; ++k) acc[mb][nb][k] = 0.f;

    // ---- prologue: H(0) cp.async + adj(0) ----
#pragma unroll
    for (int u = 0; u < 4; ++u)
        asm volatile("cp.async.cg.shared.global [%0], [%1], 16;"
                     :: "r"(hb32 + h_sts[u]), "l"(hsrc_base + u * 16) : "memory");
    asm volatile("cp.async.commit_group;" ::: "memory");

    int4 av[4];
#pragma unroll
    for (int u = 0; u < 4; ++u) av[u] = __ldg(ap[u]);
    __syncthreads();  // sdst visible

    // ---- q(0) ----
    {
        uint2 sd = *(const uint2*)(sdst_sm + lj * 8);
        __half2 sd0 = *(__half2*)&sd.x, sd1 = *(__half2*)&sd.y;
#pragma unroll
        for (int u = 0; u < 4; ++u) {
            __half2 t0 = __hadd2(sd0, sA2[u]);
            __half2 t1 = __hadd2(sd1, sA2[u]);
            __half2 m0 = __hadd2(__hmax2(t0, __hmul2(t0, c02)), nB2[u]);
            __half2 m1 = __hadd2(__hmax2(t1, __hmul2(t1, c02)), nB2[u]);
            uint32_t e0 = hexp2(*(uint32_t*)&m0);
            uint32_t e1 = hexp2(*(uint32_t*)&m1);
            uint32_t k0 = (av[u].x > 0 ? 0x3C00u : 0u) | (av[u].y > 0 ? 0x3C000000u : 0u);
            uint32_t k1 = (av[u].z > 0 ? 0x3C00u : 0u) | (av[u].w > 0 ? 0x3C000000u : 0u);
            __half2 q0 = __hmul2(*(__half2*)&e0, *(__half2*)&k0);
            __half2 q1 = __hmul2(*(__half2*)&e1, *(__half2*)&k1);
            float2 f0 = __half22float2(__hadd2(q0, q1));
            lacc[u] += f0.x + f0.y;
            *(uint2*)(qbuf + q_sts[u]) = make_uint2(*(uint32_t*)&q0, *(uint32_t*)&q1);
        }
    }
    asm volatile("cp.async.wait_group 0;" ::: "memory");
    __syncthreads();  // q(0), H(0) visible

    for (int t = 0; t < 64; ++t) {
        // ---- issue H(t+1) cp.async + adj(t+1) LDGs ----
        if (t < 63) {
            int tt = t + 1;
            uint32_t dst = hb32 + (tt & 1) * 16384;
            const char* src = hsrc_base + (size_t)tt * 64 * 256;
#pragma unroll
            for (int u = 0; u < 4; ++u)
                asm volatile("cp.async.cg.shared.global [%0], [%1], 16;"
                             :: "r"(dst + h_sts[u]), "l"(src + u * 16) : "memory");
            asm volatile("cp.async.commit_group;" ::: "memory");
#pragma unroll
            for (int u = 0; u < 4; ++u) av[u] = __ldg(ap[u] + tt * 16);
        }

        // ---- MMA on tile t ----
        uint32_t qb = qb32 + (uint32_t)((t & 1) * 8192);
        uint32_t hb = hb32 + (uint32_t)((t & 1) * 16384);
#pragma unroll
        for (int kb = 0; kb < 4; ++kb) {
            uint32_t a0[4], a1[4];
            uint32_t aaddr = qb + a_base + (uint32_t)((((2 * kb + asel) ^ arx)) << 4);
            asm volatile(
                "ldmatrix.sync.aligned.m8n8.x4.shared.b16 {%0,%1,%2,%3}, [%4];"
                : "=r"(a0[0]), "=r"(a0[1]), "=r"(a0[2]), "=r"(a0[3]) : "r"(aaddr));
            asm volatile(
                "ldmatrix.sync.aligned.m8n8.x4.shared.b16 {%0,%1,%2,%3}, [%4];"
                : "=r"(a1[0]), "=r"(a1[1]), "=r"(a1[2]), "=r"(a1[3])
                : "r"(aaddr + 2048));
            int lrow = kb * 16 + lrow_in;
            int rx = lrow & 7;
            uint32_t rowa = hb + (uint32_t)(lrow * 256);
#pragma unroll
            for (int p = 0; p < 2; ++p) {
                uint32_t baddr = rowa + (uint32_t)((((bchunk + 2 * p) ^ rx)) << 4);
                uint32_t b0, b1, b2, b3;
                asm volatile(
                    "ldmatrix.sync.aligned.m8n8.x4.trans.shared.b16 "
                    "{%0,%1,%2,%3}, [%4];"
                    : "=r"(b0), "=r"(b1), "=r"(b2), "=r"(b3) : "r"(baddr));
                mma16816(acc[0][2 * p], a0, b0, b1);
                mma16816(acc[0][2 * p + 1], a0, b2, b3);
                mma16816(acc[1][2 * p], a1, b0, b1);
                mma16816(acc[1][2 * p + 1], a1, b2, b3);
            }
        }

        // ---- compute q(t+1), STS into other buffer ----
        if (t < 63) {
            int tt = t + 1;
            char* qd = qbuf + (tt & 1) * 8192;
            uint2 sd = *(const uint2*)(sdst_sm + tt * 128 + lj * 8);
            __half2 sd0 = *(__half2*)&sd.x, sd1 = *(__half2*)&sd.y;
#pragma unroll
            for (int u = 0; u < 4; ++u) {
                __half2 t0 = __hadd2(sd0, sA2[u]);
                __half2 t1 = __hadd2(sd1, sA2[u]);
                __half2 m0 = __hadd2(__hmax2(t0, __hmul2(t0, c02)), nB2[u]);
                __half2 m1 = __hadd2(__hmax2(t1, __hmul2(t1, c02)), nB2[u]);
                uint32_t e0 = hexp2(*(uint32_t*)&m0);
                uint32_t e1 = hexp2(*(uint32_t*)&m1);
                uint32_t k0 = (av[u].x > 0 ? 0x3C00u : 0u) | (av[u].y > 0 ? 0x3C000000u : 0u);
                uint32_t k1 = (av[u].z > 0 ? 0x3C00u : 0u) | (av[u].w > 0 ? 0x3C000000u : 0u);
                __half2 q0 = __hmul2(*(__half2*)&e0, *(__half2*)&k0);
                __half2 q1 = __hmul2(*(__half2*)&e1, *(__half2*)&k1);
                float2 f0 = __half22float2(__hadd2(q0, q1));
                lacc[u] += f0.x + f0.y;
                *(uint2*)(qd + q_sts[u]) = make_uint2(*(uint32_t*)&q0, *(uint32_t*)&q1);
            }
            asm volatile("cp.async.wait_group 0;" ::: "memory");
        }
        __syncthreads();
    }

    // ---- partial l: reduce over 16 lanes sharing each row ----
#pragma unroll
    for (int u = 0; u < 4; ++u) {
        lacc[u] += __shfl_xor_sync(0xffffffffu, lacc[u], 1);
        lacc[u] += __shfl_xor_sync(0xffffffffu, lacc[u], 2);
        lacc[u] += __shfl_xor_sync(0xffffffffu, lacc[u], 4);
        lacc[u] += __shfl_xor_sync(0xffffffffu, lacc[u], 8);
    }
    if (lj == 0) {
#pragma unroll
        for (int u = 0; u < 4; ++u)
            g_lpart[jh * Nn + i0 + qrows[u]] = lacc[u];
    }

    // ---- write unnormalized partials ----
    int g = lane >> 2, c = lane & 3;
    float* pb = g_part + (size_t)jh * Nn * Ff;
#pragma unroll
    for (int mb = 0; mb < 2; ++mb) {
        int rA = ws * 32 + mb * 16 + g, rB = rA + 8;
#pragma unroll
        for (int nb = 0; nb < 4; ++nb) {
            int col = ns * 32 + nb * 8 + 2 * c;
            *(float2*)(pb + (size_t)(i0 + rA) * Ff + col) =
                make_float2(acc[mb][nb][0], acc[mb][nb][1]);
            *(float2*)(pb + (size_t)(i0 + rB) * Ff + col) =
                make_float2(acc[mb][nb][2], acc[mb][nb][3]);
        }
    }
}

// ---------------------------------------------------------------------------
// K_combine: out = (p0 + p1) / (l0 + l1), float4 per thread
// ---------------------------------------------------------------------------
__global__ void __launch_bounds__(256) k_combine(float* __restrict__ out) {
    int idx4 = blockIdx.x * 256 + threadIdx.x;
    int row = idx4 >> 5;  // 32 float4 per row
    float il = 1.0f / (g_lpart[row] + g_lpart[Nn + row]);
    const float4* p0 = (const float4*)g_part;
    const float4* p1 = (const float4*)(g_part + (size_t)Nn * Ff);
    float4 a = p0[idx4], b = p1[idx4];
    float4 o;
    o.x = (a.x + b.x) * il;
    o.y = (a.y + b.y) * il;
    o.z = (a.z + b.z) * il;
    o.w = (a.w + b.w) * il;
    ((float4*)out)[idx4] = o;
}

// ---------------------------------------------------------------------------
extern "C" void kernel_launch(void* const* d_in, const int* in_sizes, int n_in,
                              void* d_out, int out_size) {
    const float* x   = (const float*)d_in[0];
    const int*   adj = (const int*)d_in[1];
    const float* W   = (const float*)d_in[2];
    const float* a   = (const float*)d_in[3];
    float* out = (float*)d_out;

    cudaFuncSetAttribute(k_main, cudaFuncAttributeMaxDynamicSharedMemorySize, SMEM_SZ);

    k_xw<<<Nn / 32, 256>>>(x, W, a);
    k_main<<<Nn / 64 * 2, 256, SMEM_SZ>>>(adj);
    k_combine<<<Nn * Ff / 4 / 256, 256>>>(out);
}